// round 13
// baseline (speedup 1.0000x reference)
#include <cuda_runtime.h>

typedef unsigned long long u64;

// Packed fp32x2 ops (Blackwell sm_103a). ptxas never auto-fuses these from C++;
// they must come from PTX (SASS_QUICKREF "patterns absent from ptxas output").
__device__ __forceinline__ u64 add2(u64 a, u64 b) {
    u64 d; asm("add.rn.f32x2 %0, %1, %2;" : "=l"(d) : "l"(a), "l"(b)); return d;
}
__device__ __forceinline__ u64 fma2(u64 a, u64 b, u64 c) {
    u64 d; asm("fma.rn.f32x2 %0, %1, %2, %3;" : "=l"(d) : "l"(a), "l"(b), "l"(c)); return d;
}
__device__ __forceinline__ u64 dup_lo(u64 a) {
    u64 d;
    asm("{\n\t.reg .b32 lo, hi;\n\tmov.b64 {lo, hi}, %1;\n\tmov.b64 %0, {lo, lo};\n\t}"
        : "=l"(d) : "l"(a));
    return d;
}
__device__ __forceinline__ u64 dup_hi(u64 a) {
    u64 d;
    asm("{\n\t.reg .b32 lo, hi;\n\tmov.b64 {lo, hi}, %1;\n\tmov.b64 %0, {hi, hi};\n\t}"
        : "=l"(d) : "l"(a));
    return d;
}

#define DIN   112   // input spatial extent (D = H = W)
#define DOUT  111   // output extent per dim (VALID 2-window)
#define MCH   16    // channels
#define TH    4     // output h-rows per block
#define CS4   5     // float4 slots per smem column (4 data + 1 pad -> 80B stride)
#define NTHR  256   // threads per block

// R13: STREAMED-K matmul. Evidence chain: R9 (128thr, regs=128) = spill-free,
// 192MB DRAM (ideal), 107us but issue=15% (too few warps). R10 (cap 64) and
// R12 (cap 85, regs=80) both spilled — demand of the "materialize agg[16],
// then matmul" structure is ~100 regs, so every 256-thread cap spilled
// (582-881MB DRAM of LDL/STL round-trips). Fix is structural: stream each
// 4-channel k-slot — load 4 columns' slot, form 2 agg pairs, immediately
// consume through 32 fma2 into persistent o[8], discard. Demand ~60-70 regs
// -> (256,3)'s 85 cap is now above demand: 24 warps/SM AND spill-free.
// Phase 1: build p[h'][w'][c] = x[d0] + x[d0+1] for (TH+1) h-rows into padded
//          SMEM (80B column stride -> conflict-free LDS.128 in phase 2).
// Phase 2: tid -> (row = tid>>6, wl = tid&63); per window: streamed agg+matmul,
//          out = (window_sum) @ (M/8)^T, M^T pre-scaled in SMEM (broadcast LDS).
__global__ __launch_bounds__(NTHR, 3)
void sdd3_kernel(const float* __restrict__ x,
                 const float* __restrict__ M,
                 float* __restrict__ out)
{
    __shared__ float4 sP[(TH + 1) * DIN * CS4];      // 5*112*5*16B = 44800 B
    __shared__ __align__(16) float sM[MCH * MCH];    // transposed, pre-scaled by 1/8

    const int tid = threadIdx.x;
    const int d0 = blockIdx.y;            // output d index: needs input d0, d0+1
    const int h0 = blockIdx.x * TH;       // first output h row of this tile
    const int rows_out = min(TH, DOUT - h0);
    const int rows_in  = rows_out + 1;

    // ---------------- Phase 1: d-pair sums into padded SMEM ----------------
    const size_t slice = (size_t)DIN * DIN * MCH;
    const float4* __restrict__ xa =
        (const float4*)(x + (size_t)d0 * slice + (size_t)h0 * DIN * MCH);
    const float4* __restrict__ xb = (const float4*)((const float*)xa + slice);

    const int n4 = rows_in * DIN * 4;     // float4 elements to stage
    for (int i = tid; i < n4; i += NTHR) {
        float4 a = xa[i];
        float4 b = xb[i];
        float4 s = make_float4(a.x + b.x, a.y + b.y, a.z + b.z, a.w + b.w);
        sP[(i >> 2) * CS4 + (i & 3)] = s;   // column-padded layout
    }
    // Stage M^T * 0.125: sM[j*16 + i] = M[i*16 + j] / 8
    for (int t = tid; t < MCH * MCH; t += NTHR) {
        int i = t >> 4, j = t & 15;
        sM[j * MCH + i] = M[t] * 0.125f;
    }
    __syncthreads();

    // ---------------- Phase 2: streamed window combine + f32x2 matmul ------
    const int row = tid >> 6;     // output row within tile (2 warps per row)
    const int wl  = tid & 63;     // starting w lane
    if (row < rows_out) {
        const char* sbase = (const char*)sP;
        for (int w = wl; w < DOUT; w += 64) {
            const int c00 = (row * DIN + w) * 80;   // bytes; 80B per column
            const ulonglong2* p00 = (const ulonglong2*)(sbase + c00);
            const ulonglong2* p01 = (const ulonglong2*)(sbase + c00 + 80);
            const ulonglong2* p10 = (const ulonglong2*)(sbase + c00 + DIN * 80);
            const ulonglong2* p11 = (const ulonglong2*)(sbase + c00 + DIN * 80 + 80);

            u64 o[8];     // o[p] = output channels (2p, 2p+1)
            #pragma unroll
            for (int k = 0; k < 8; ++k) o[k] = 0ull;

            // Stream k-slots: produce agg channels 4k..4k+3, consume them
            // immediately (32 fma2), never keep the full agg vector live.
            #pragma unroll
            for (int k = 0; k < 4; ++k) {
                ulonglong2 a0 = p00[k];
                ulonglong2 a1 = p01[k];
                ulonglong2 b0 = p10[k];
                ulonglong2 b1 = p11[k];
                u64 agg0 = add2(add2(a0.x, a1.x), add2(b0.x, b1.x)); // ch 4k,4k+1
                u64 agg1 = add2(add2(a0.y, a1.y), add2(b0.y, b1.y)); // ch 4k+2,4k+3

                #pragma unroll
                for (int jj = 0; jj < 4; ++jj) {          // j = 4k + jj
                    u64 s = (jj == 0) ? dup_lo(agg0)
                          : (jj == 1) ? dup_hi(agg0)
                          : (jj == 2) ? dup_lo(agg1)
                                      : dup_hi(agg1);
                    const ulonglong2* mrow =
                        (const ulonglong2*)&sM[(4 * k + jj) * MCH];
                    #pragma unroll
                    for (int q = 0; q < 4; ++q) {
                        ulonglong2 mv = mrow[q];   // (M/8)^T row j, out ch 4q..4q+3
                        o[2 * q]     = fma2(s, mv.x, o[2 * q]);
                        o[2 * q + 1] = fma2(s, mv.y, o[2 * q + 1]);
                    }
                }
            }

            ulonglong2* op = (ulonglong2*)(out +
                (((size_t)d0 * DOUT + (size_t)(h0 + row)) * DOUT + (size_t)w) * MCH);
            #pragma unroll
            for (int k = 0; k < 4; ++k)
                op[k] = make_ulonglong2(o[2 * k], o[2 * k + 1]);
        }
    }
}

extern "C" void kernel_launch(void* const* d_in, const int* in_sizes, int n_in,
                              void* d_out, int out_size)
{
    const float* x = (const float*)d_in[0];
    const float* M = (const float*)d_in[1];
    // Robustness: detect argument order by size (M is 16*16 = 256 elements).
    if (n_in >= 2 && in_sizes[0] == MCH * MCH) {
        x = (const float*)d_in[1];
        M = (const float*)d_in[0];
    }
    dim3 grid((DOUT + TH - 1) / TH, DOUT);   // (28, 111)
    sdd3_kernel<<<grid, NTHR>>>(x, M, (float*)d_out);
}

// round 15
// speedup vs baseline: 1.2444x; 1.2444x over previous
#include <cuda_runtime.h>

typedef unsigned long long u64;

// Packed fp32x2 ops (Blackwell sm_103a). ptxas never auto-fuses these from C++;
// they must come from PTX (SASS_QUICKREF "patterns absent from ptxas output").
__device__ __forceinline__ u64 add2(u64 a, u64 b) {
    u64 d; asm("add.rn.f32x2 %0, %1, %2;" : "=l"(d) : "l"(a), "l"(b)); return d;
}
__device__ __forceinline__ u64 fma2(u64 a, u64 b, u64 c) {
    u64 d; asm("fma.rn.f32x2 %0, %1, %2, %3;" : "=l"(d) : "l"(a), "l"(b), "l"(c)); return d;
}
__device__ __forceinline__ u64 dup_lo(u64 a) {
    u64 d;
    asm("{\n\t.reg .b32 lo, hi;\n\tmov.b64 {lo, hi}, %1;\n\tmov.b64 %0, {lo, lo};\n\t}"
        : "=l"(d) : "l"(a));
    return d;
}
__device__ __forceinline__ u64 dup_hi(u64 a) {
    u64 d;
    asm("{\n\t.reg .b32 lo, hi;\n\tmov.b64 {lo, hi}, %1;\n\tmov.b64 %0, {hi, hi};\n\t}"
        : "=l"(d) : "l"(a));
    return d;
}

#define DIN   112   // input spatial extent (D = H = W)
#define DOUT  111   // output extent per dim (VALID 2-window)
#define MCH   16    // channels
#define TH    4     // output h-rows per block
#define CS4   5     // float4 slots per smem column (4 data + 1 pad -> 80B stride)
#define NTHR  128   // threads per block

// R14 (re-land; previous attempt hit infra failure, never ran): back to the
// proven-clean (128,4) point (R9: regs=128 free, 191MB DRAM ideal, 107us) —
// every attempt to raise warp count (R10 cap64 / R12-13 cap85) hit the reg
// cap and poisoned DRAM with spill traffic (582-885MB). At 16 warps the
// kernel is latency-bound (issue 15%, no pipe saturated), so this round buys
// ILP instead of occupancy: each thread processes TWO windows (w, w+64)
// concurrently. The 64 per-window sM broadcast LDS (largest issue-slot
// consumer) are shared between both windows (-18% warp inst), and two
// independent o[8] chains + two column streams double latency overlap.
// k-slots streamed; outer 2-iter loop kept rolled to bound the live set
// (~75 regs < 128 cap -> spill-free).
__global__ __launch_bounds__(NTHR, 4)
void sdd3_kernel(const float* __restrict__ x,
                 const float* __restrict__ M,
                 float* __restrict__ out)
{
    __shared__ float4 sP[(TH + 1) * DIN * CS4];      // 5*112*5*16B = 44800 B
    __shared__ __align__(16) float sM[MCH * MCH];    // transposed, pre-scaled by 1/8

    const int tid = threadIdx.x;
    const int d0 = blockIdx.y;            // output d index: needs input d0, d0+1
    const int h0 = blockIdx.x * TH;       // first output h row of this tile
    const int rows_out = min(TH, DOUT - h0);
    const int rows_in  = rows_out + 1;

    // ---------------- Phase 1: d-pair sums into padded SMEM ----------------
    const size_t slice = (size_t)DIN * DIN * MCH;
    const float4* __restrict__ xa =
        (const float4*)(x + (size_t)d0 * slice + (size_t)h0 * DIN * MCH);
    const float4* __restrict__ xb = (const float4*)((const float*)xa + slice);

    const int n4 = rows_in * DIN * 4;     // float4 elements to stage
    for (int i = tid; i < n4; i += NTHR) {
        float4 a = xa[i];
        float4 b = xb[i];
        float4 s = make_float4(a.x + b.x, a.y + b.y, a.z + b.z, a.w + b.w);
        sP[(i >> 2) * CS4 + (i & 3)] = s;   // column-padded layout
    }
    // Stage M^T * 0.125: sM[j*16 + i] = M[i*16 + j] / 8
    for (int t = tid; t < MCH * MCH; t += NTHR) {
        int i = t >> 4, j = t & 15;
        sM[j * MCH + i] = M[t] * 0.125f;
    }
    __syncthreads();

    // ------ Phase 2: dual-window streamed combine + shared-M f32x2 matmul ---
    const int row = tid >> 5;     // output row within tile (1 warp per row)
    const int wl  = tid & 31;     // w lane 0..31
    if (row < rows_out) {
        const char* sbase = (const char*)sP;
        const size_t orow =
            (((size_t)d0 * DOUT + (size_t)(h0 + row)) * DOUT) * MCH;

        #pragma unroll 1
        for (int it = 0; it < 2; ++it) {
            const int w0 = wl + it * 32;            // 0..63  (always valid)
            const int w1 = w0 + 64;                  // 64..127
            const bool v1 = (w1 < DOUT);
            const int w1c = v1 ? w1 : w0;            // clamp dead loads safely

            const int cA = (row * DIN + w0) * 80;    // bytes; 80B per column
            const int cB = (row * DIN + w1c) * 80;
            const ulonglong2* pA00 = (const ulonglong2*)(sbase + cA);
            const ulonglong2* pA01 = (const ulonglong2*)(sbase + cA + 80);
            const ulonglong2* pA10 = (const ulonglong2*)(sbase + cA + DIN * 80);
            const ulonglong2* pA11 = (const ulonglong2*)(sbase + cA + DIN * 80 + 80);
            const ulonglong2* pB00 = (const ulonglong2*)(sbase + cB);
            const ulonglong2* pB01 = (const ulonglong2*)(sbase + cB + 80);
            const ulonglong2* pB10 = (const ulonglong2*)(sbase + cB + DIN * 80);
            const ulonglong2* pB11 = (const ulonglong2*)(sbase + cB + DIN * 80 + 80);

            u64 oA[8], oB[8];    // win0 / win1 output channel pairs
            #pragma unroll
            for (int k = 0; k < 8; ++k) { oA[k] = 0ull; oB[k] = 0ull; }

            // Stream k-slots: produce agg channels 4k..4k+3 for BOTH windows,
            // consume immediately; mv loads shared across windows.
            #pragma unroll
            for (int k = 0; k < 4; ++k) {
                ulonglong2 a0 = pA00[k], a1 = pA01[k], a2 = pA10[k], a3 = pA11[k];
                u64 aggA0 = add2(add2(a0.x, a1.x), add2(a2.x, a3.x));
                u64 aggA1 = add2(add2(a0.y, a1.y), add2(a2.y, a3.y));
                ulonglong2 b0 = pB00[k], b1 = pB01[k], b2 = pB10[k], b3 = pB11[k];
                u64 aggB0 = add2(add2(b0.x, b1.x), add2(b2.x, b3.x));
                u64 aggB1 = add2(add2(b0.y, b1.y), add2(b2.y, b3.y));

                #pragma unroll
                for (int jj = 0; jj < 4; ++jj) {          // j = 4k + jj
                    u64 sA = (jj == 0) ? dup_lo(aggA0)
                           : (jj == 1) ? dup_hi(aggA0)
                           : (jj == 2) ? dup_lo(aggA1)
                                       : dup_hi(aggA1);
                    u64 sB = (jj == 0) ? dup_lo(aggB0)
                           : (jj == 1) ? dup_hi(aggB0)
                           : (jj == 2) ? dup_lo(aggB1)
                                       : dup_hi(aggB1);
                    const ulonglong2* mrow =
                        (const ulonglong2*)&sM[(4 * k + jj) * MCH];
                    #pragma unroll
                    for (int q = 0; q < 4; ++q) {
                        ulonglong2 mv = mrow[q];   // shared across both windows
                        oA[2 * q]     = fma2(sA, mv.x, oA[2 * q]);
                        oA[2 * q + 1] = fma2(sA, mv.y, oA[2 * q + 1]);
                        oB[2 * q]     = fma2(sB, mv.x, oB[2 * q]);
                        oB[2 * q + 1] = fma2(sB, mv.y, oB[2 * q + 1]);
                    }
                }
            }

            ulonglong2* opA = (ulonglong2*)(out + orow + (size_t)w0 * MCH);
            #pragma unroll
            for (int k = 0; k < 4; ++k)
                opA[k] = make_ulonglong2(oA[2 * k], oA[2 * k + 1]);
            if (v1) {
                ulonglong2* opB = (ulonglong2*)(out + orow + (size_t)w1 * MCH);
                #pragma unroll
                for (int k = 0; k < 4; ++k)
                    opB[k] = make_ulonglong2(oB[2 * k], oB[2 * k + 1]);
            }
        }
    }
}

extern "C" void kernel_launch(void* const* d_in, const int* in_sizes, int n_in,
                              void* d_out, int out_size)
{
    const float* x = (const float*)d_in[0];
    const float* M = (const float*)d_in[1];
    // Robustness: detect argument order by size (M is 16*16 = 256 elements).
    if (n_in >= 2 && in_sizes[0] == MCH * MCH) {
        x = (const float*)d_in[1];
        M = (const float*)d_in[0];
    }
    dim3 grid((DOUT + TH - 1) / TH, DOUT);   // (28, 111)
    sdd3_kernel<<<grid, NTHR>>>(x, M, (float*)d_out);
}